// round 7
// baseline (speedup 1.0000x reference)
#include <cuda_runtime.h>

// MeanAggregator, multi-pass L2 temporal blocking + ballot-compacted gathers.
// out[b,:] = mean_k table[neighs[b,k],:], B=50000, K=32, table 500000x128 f32.
//
// 4 kernel launches; pass p gathers only rows in segment [p*125K,(p+1)*125K)
// (64MB -> L2-resident together with out 26MB + idx 13MB). Kernel boundaries
// give the global ordering that in-kernel segmentation lacks (R6 lesson).
// Within a pass: warp ballot of in-segment lanes (~8 expected), compact up to
// 8 bits per burst -> 4 independent 256-bit paired gathers (MLP=4), instead of
// 16 predicated serial iterations (R5 lesson).

#define BATCH   50000
#define DEGREE  32
#define D_FEAT  128
#define WARPS_PER_BLOCK 8
#define THREADS (WARPS_PER_BLOCK * 32)
#define NSEG    4
#define SEG     (500000 / NSEG)
#define FULL    0xffffffffu

__device__ int g_idx_is64;

// int64 indices in [0,500000) have all odd 32-bit words == 0; int32 data has
// random values there (P(128 zeros) ~ 0).
__global__ void detect_idx_dtype(const unsigned int* __restrict__ n32)
{
    bool all_zero = true;
    #pragma unroll
    for (int i = 1; i < 256; i += 2) {
        if (n32[i] != 0u) { all_zero = false; break; }
    }
    g_idx_is64 = all_zero ? 1 : 0;
}

struct F8 { float v[8]; };

__device__ __forceinline__ F8 ldg_evict_last_v8(const float* p)
{
    F8 r;
    asm volatile(
        "ld.global.nc.L2::evict_last.v8.b32 {%0,%1,%2,%3,%4,%5,%6,%7}, [%8];"
        : "=f"(r.v[0]), "=f"(r.v[1]), "=f"(r.v[2]), "=f"(r.v[3]),
          "=f"(r.v[4]), "=f"(r.v[5]), "=f"(r.v[6]), "=f"(r.v[7])
        : "l"(p));
    return r;
}

__global__ __launch_bounds__(THREADS)
void mean_agg_pass(const void* __restrict__ neighs_raw,
                   const float* __restrict__ table,  // [500000, 128] f32
                   float* __restrict__ out,          // [50000, 128] raw sums until last pass
                   int pass)
{
    const int warp = (blockIdx.x * THREADS + threadIdx.x) >> 5;
    const int lane = threadIdx.x & 31;
    if (warp >= BATCH) return;

    const int half = lane >> 4;   // which row of a gathered pair this lane serves
    const int sub  = lane & 15;   // which 32B slice of the 512B row

    // Coalesced load of this node's 32 indices (lane k -> index k). Normal
    // caching: 13MB, L2-resident after pass 0.
    long long my_idx;
    if (g_idx_is64) {
        my_idx = __ldg(&((const long long*)neighs_raw)[(size_t)warp * DEGREE + lane]);
    } else {
        my_idx = (long long)__ldg(&((const int*)neighs_raw)[(size_t)warp * DEGREE + lane]);
    }

    const long long lo = (long long)pass * SEG;
    const long long hi = lo + SEG;

    float acc[8] = {0.f, 0.f, 0.f, 0.f, 0.f, 0.f, 0.f, 0.f};

    unsigned m = __ballot_sync(FULL, my_idx >= lo && my_idx < hi);

    while (m) {
        // Compact up to 8 set bits -> 4 paired gathers (MLP=4 per lane).
        int b[8];
        #pragma unroll
        for (int j = 0; j < 8; ++j) {
            b[j] = m ? (__ffs(m) - 1) : -1;
            m &= (m - 1);
        }

        F8 r[4];
        bool val[4];
        #pragma unroll
        for (int j = 0; j < 4; ++j) {
            const int src = half ? b[2 * j + 1] : b[2 * j];
            val[j] = (src >= 0);
            const long long idx = __shfl_sync(FULL, my_idx, val[j] ? src : 0);
            if (val[j])
                r[j] = ldg_evict_last_v8(&table[(size_t)idx * D_FEAT + sub * 8]);
        }
        #pragma unroll
        for (int j = 0; j < 4; ++j) {
            if (val[j]) {
                #pragma unroll
                for (int i = 0; i < 8; ++i) acc[i] += r[j].v[i];
            }
        }
    }

    // Fold halves: lanes l and l^16 hold the same columns, disjoint neighbor sets.
    #pragma unroll
    for (int i = 0; i < 8; ++i)
        acc[i] += __shfl_xor_sync(FULL, acc[i], 16);

    if (half == 0) {
        float* dst = out + (size_t)warp * D_FEAT + sub * 8;
        if (pass != 0) {
            // Partial sums written by the previous pass: L2-resident (26MB),
            // normal caching for write-back reuse.
            const float4 p0 = ((const float4*)dst)[0];
            const float4 p1 = ((const float4*)dst)[1];
            acc[0] += p0.x; acc[1] += p0.y; acc[2] += p0.z; acc[3] += p0.w;
            acc[4] += p1.x; acc[5] += p1.y; acc[6] += p1.z; acc[7] += p1.w;
        }
        if (pass == NSEG - 1) {
            const float s = 1.0f / (float)DEGREE;
            #pragma unroll
            for (int i = 0; i < 8; ++i) acc[i] *= s;
        }
        ((float4*)dst)[0] = make_float4(acc[0], acc[1], acc[2], acc[3]);
        ((float4*)dst)[1] = make_float4(acc[4], acc[5], acc[6], acc[7]);
    }
}

extern "C" void kernel_launch(void* const* d_in, const int* in_sizes, int n_in,
                              void* d_out, int out_size)
{
    const void*  neighs = d_in[0];
    const float* table  = (const float*)d_in[1];
    float*       out    = (float*)d_out;

    detect_idx_dtype<<<1, 1>>>((const unsigned int*)neighs);

    const int blocks = (BATCH + WARPS_PER_BLOCK - 1) / WARPS_PER_BLOCK;
    for (int p = 0; p < NSEG; ++p)
        mean_agg_pass<<<blocks, THREADS>>>(neighs, table, out, p);
}